// round 1
// baseline (speedup 1.0000x reference)
#include <cuda_runtime.h>
#include <math.h>

// Problem constants
#define NROWS 16384
#define DDIM  64

// GEMM tiling
#define BM 128
#define BN 64
#define TM 8
#define TN 4
#define NTHREADS 256
#define NROWBLOCKS (NROWS / BM)   // 128
#define NCOLTILES  (NROWS / BN)   // 256

// log2(e)/tau folded into z1 so logits come out in base-2
#define SCALE_A 28.853900817779268f   // log2(e)/0.05
#define LN2F    0.6931471805599453f

// Scratch (no allocations allowed in kernel_launch)
__device__ float g_z1t[DDIM * NROWS];   // [k][n], scaled by log2e/tau / ||z1_n||
__device__ float g_z2t[DDIM * NROWS];   // [k][n], scaled by 1 / ||z2_n||
__device__ float g_partials[NROWBLOCKS];

// ---------------------------------------------------------------------------
// Kernel 1: fused L2-normalize + transpose to k-major + scale fold.
// One warp per row; each lane owns elements (lane, lane+32).
// ---------------------------------------------------------------------------
__global__ void normalize_kernel(const float* __restrict__ z1,
                                 const float* __restrict__ z2) {
    int row  = blockIdx.x * (blockDim.x >> 5) + (threadIdx.x >> 5);
    int lane = threadIdx.x & 31;
    if (row >= 2 * NROWS) return;

    const float* src;
    float* dst;
    float scale;
    int r;
    if (row < NROWS) { src = z1; dst = g_z1t; r = row;          scale = SCALE_A; }
    else             { src = z2; dst = g_z2t; r = row - NROWS;  scale = 1.0f;    }

    float v0 = src[r * DDIM + lane];
    float v1 = src[r * DDIM + lane + 32];
    float ss = v0 * v0 + v1 * v1;
    #pragma unroll
    for (int off = 16; off; off >>= 1)
        ss += __shfl_xor_sync(0xffffffffu, ss, off);
    float nrm = sqrtf(ss);
    float inv = scale / fmaxf(nrm, 1e-12f);
    dst[lane * NROWS + r]        = v0 * inv;
    dst[(lane + 32) * NROWS + r] = v1 * inv;
}

// ---------------------------------------------------------------------------
// Kernel 2: fused GEMM (sim/tau in base-2 logits) + row-wise online logsumexp.
// Block = 128 rows; loops over 256 column tiles of 64.
// Static smem exactly 48KB (As 32KB + Bs 16KB) -> no attribute calls needed.
// ---------------------------------------------------------------------------
__global__ void __launch_bounds__(NTHREADS, 1) gemm_lse_kernel() {
    __shared__ float As[DDIM * BM];   // [k][m], 32768 B
    __shared__ float Bs[DDIM * BN];   // [k][n], 16384 B

    const int tid = threadIdx.x;
    const int tx  = tid & 15;         // 16 col-threads  (cover BN=64, TN=4)
    const int ty  = tid >> 4;         // 16 row-threads  (cover BM=128, TM=8)
    const int rowBase = blockIdx.x * BM;

    // Load A tile once (k-major source -> straight coalesced copy)
    {
        float4* As4 = (float4*)As;
        #pragma unroll
        for (int idx = tid; idx < DDIM * BM / 4; idx += NTHREADS) {
            int k  = idx >> 5;        // 32 float4 per 128-wide row
            int m4 = idx & 31;
            As4[idx] = *(const float4*)&g_z1t[k * NROWS + rowBase + m4 * 4];
        }
    }

    float mrun[TM], srun[TM], pos[TM];
    unsigned posMask = 0u;
    #pragma unroll
    for (int i = 0; i < TM; i++) { mrun[i] = -1e30f; srun[i] = 0.f; pos[i] = 0.f; }

    for (int tile = 0; tile < NCOLTILES; tile++) {
        __syncthreads();              // prior readers of Bs done (also covers As on iter 0)
        {
            float4* Bs4 = (float4*)Bs;
            int colBase = tile * BN;
            #pragma unroll
            for (int idx = tid; idx < DDIM * BN / 4; idx += NTHREADS) {
                int k  = idx >> 4;    // 16 float4 per 64-wide row
                int n4 = idx & 15;
                Bs4[idx] = *(const float4*)&g_z2t[k * NROWS + colBase + n4 * 4];
            }
        }
        __syncthreads();

        float acc[TM][TN];
        #pragma unroll
        for (int i = 0; i < TM; i++)
            #pragma unroll
            for (int j = 0; j < TN; j++) acc[i][j] = 0.f;

        const float4* As4 = (const float4*)As;
        const float4* Bs4 = (const float4*)Bs;
        #pragma unroll 8
        for (int k = 0; k < DDIM; k++) {
            float4 a0 = As4[k * 32 + ty * 2];
            float4 a1 = As4[k * 32 + ty * 2 + 1];
            float4 b  = Bs4[k * 16 + tx];
            float a[TM] = {a0.x, a0.y, a0.z, a0.w, a1.x, a1.y, a1.z, a1.w};
            float bb[TN] = {b.x, b.y, b.z, b.w};
            #pragma unroll
            for (int i = 0; i < TM; i++)
                #pragma unroll
                for (int j = 0; j < TN; j++)
                    acc[i][j] = fmaf(a[i], bb[j], acc[i][j]);
        }

        // Online logsumexp update (base-2 logits)
        #pragma unroll
        for (int i = 0; i < TM; i++) {
            float mx = acc[i][0];
            #pragma unroll
            for (int j = 1; j < TN; j++) mx = fmaxf(mx, acc[i][j]);
            float newm = fmaxf(mrun[i], mx);
            float s = srun[i] * exp2f(mrun[i] - newm);
            #pragma unroll
            for (int j = 0; j < TN; j++) s += exp2f(acc[i][j] - newm);
            srun[i] = s;
            mrun[i] = newm;
        }

        // Diagonal (positive) extraction: diag intact in the sum is exactly
        // equivalent to [pos, masked-row] logits (mask underflows to 0).
        int colBase = tile * BN;
        if (colBase >= rowBase && colBase < rowBase + BM) {
            #pragma unroll
            for (int i = 0; i < TM; i++)
                #pragma unroll
                for (int j = 0; j < TN; j++)
                    if (rowBase + ty * TM + i == colBase + tx * TN + j) {
                        pos[i] = acc[i][j];
                        posMask |= (1u << i);
                    }
        }
    }

    __syncthreads();
    // Reduction scratch overlays As (32KB >= 128*16*2*4 + 128*4 bytes)
    float* redM   = As;               // [128][16]
    float* redS   = As + 2048;        // [128][16]
    float* posArr = As + 4096;        // [128]
    #pragma unroll
    for (int i = 0; i < TM; i++) {
        int r = ty * TM + i;
        redM[r * 16 + tx] = mrun[i];
        redS[r * 16 + tx] = srun[i];
        if (posMask & (1u << i)) posArr[r] = pos[i];
    }
    __syncthreads();

    float myloss = 0.f;
    if (tid < BM) {
        int r = tid;
        float m = redM[r * 16];
        #pragma unroll
        for (int t = 1; t < 16; t++) m = fmaxf(m, redM[r * 16 + t]);
        float s = 0.f;
        #pragma unroll
        for (int t = 0; t < 16; t++)
            s += redS[r * 16 + t] * exp2f(redM[r * 16 + t] - m);
        float lse2 = m + log2f(s);
        myloss = (lse2 - posArr[r]) * LN2F;
    }
    __syncthreads();

    float* red = As;                  // reuse again for block sum
    red[tid] = myloss;
    __syncthreads();
    #pragma unroll
    for (int off = 128; off; off >>= 1) {
        if (tid < off) red[tid] += red[tid + off];
        __syncthreads();
    }
    if (tid == 0) g_partials[blockIdx.x] = red[0];
}

// ---------------------------------------------------------------------------
// Kernel 3: deterministic final reduction
// ---------------------------------------------------------------------------
__global__ void finalize_kernel(float* __restrict__ out) {
    __shared__ float red[NROWBLOCKS];
    int tid = threadIdx.x;
    red[tid] = g_partials[tid];
    __syncthreads();
    #pragma unroll
    for (int off = 64; off; off >>= 1) {
        if (tid < off) red[tid] += red[tid + off];
        __syncthreads();
    }
    if (tid == 0) out[0] = red[0] * (1.0f / (float)NROWS);
}

// ---------------------------------------------------------------------------
extern "C" void kernel_launch(void* const* d_in, const int* in_sizes, int n_in,
                              void* d_out, int out_size) {
    const float* z1 = (const float*)d_in[0];
    const float* z2 = (const float*)d_in[1];
    float* out = (float*)d_out;

    normalize_kernel<<<(2 * NROWS) / 8, 256>>>(z1, z2);
    gemm_lse_kernel<<<NROWBLOCKS, NTHREADS>>>();
    finalize_kernel<<<1, NROWBLOCKS>>>(out);
}

// round 3
// speedup vs baseline: 6.7761x; 6.7761x over previous
#include <cuda_runtime.h>
#include <cuda_fp16.h>
#include <cstdint>
#include <math.h>

#define NROWS 16384
#define DDIM  64
#define BM    128
#define BN    128
#define NTILES  (NROWS / BN)   // 128
#define NBLOCKS (NROWS / BM)   // 128
#define NTHR  512
#define SCALE_A 28.853900817779268f   // log2(e)/tau
#define LN2F    0.6931471805599453f

__device__ __half g_ah[NROWS * DDIM];   // z1n * log2(e)/tau  [m][k]
__device__ __half g_bh[NROWS * DDIM];   // z2n               [n][k]
__device__ float  g_partials[NBLOCKS];

__device__ __forceinline__ uint32_t smem_u32(const void* p) {
    uint32_t a;
    asm("{ .reg .u64 t; cvta.to.shared.u64 t, %1; cvt.u32.u64 %0, t; }" : "=r"(a) : "l"(p));
    return a;
}
__device__ __forceinline__ float ex2f(float x) {
    float r; asm("ex2.approx.f32 %0, %1;" : "=f"(r) : "f"(x)); return r;
}
#define LDSM_X4(r0, r1, r2, r3, addr) \
    asm volatile("ldmatrix.sync.aligned.m8n8.x4.shared.b16 {%0,%1,%2,%3}, [%4];" \
        : "=r"(r0), "=r"(r1), "=r"(r2), "=r"(r3) : "r"(addr))
#define MMA16816(c, a, b) \
    asm volatile("mma.sync.aligned.m16n8k16.row.col.f32.f16.f16.f32 " \
        "{%0,%1,%2,%3}, {%4,%5,%6,%7}, {%8,%9}, {%0,%1,%2,%3};" \
        : "+f"((c)[0]), "+f"((c)[1]), "+f"((c)[2]), "+f"((c)[3]) \
        : "r"((a)[0]), "r"((a)[1]), "r"((a)[2]), "r"((a)[3]), "r"((b)[0]), "r"((b)[1]))
#define CP_ASYNC16(dst, src) \
    asm volatile("cp.async.cg.shared.global [%0], [%1], 16;" :: "r"(dst), "l"(src))
#define CP_COMMIT()  asm volatile("cp.async.commit_group;" ::: "memory")
#define CP_WAIT(n)   asm volatile("cp.async.wait_group %0;" :: "n"(n) : "memory")

// ─────────────── Kernel 1: L2-normalize + fp16 quantize + scale fold ────────
__global__ void normalize_kernel(const float* __restrict__ z1,
                                 const float* __restrict__ z2) {
    int row  = blockIdx.x * (blockDim.x >> 5) + (threadIdx.x >> 5);
    int lane = threadIdx.x & 31;
    const float* src; __half* dst; float scale; int r;
    if (row < NROWS) { src = z1; dst = g_ah; r = row;          scale = SCALE_A; }
    else             { src = z2; dst = g_bh; r = row - NROWS;  scale = 1.0f;    }

    float2 v = ((const float2*)(src + (size_t)r * DDIM))[lane];
    float ss = v.x * v.x + v.y * v.y;
    #pragma unroll
    for (int off = 16; off; off >>= 1)
        ss += __shfl_xor_sync(0xffffffffu, ss, off);
    float inv = scale / fmaxf(sqrtf(ss), 1e-12f);
    ((__half2*)(dst + (size_t)r * DDIM))[lane] = __floats2half2_rn(v.x * inv, v.y * inv);
}

// ─────── Kernel 2: fp16 mma.sync GEMM + fused row-wise exp2-sum (LSE) ───────
// smem: B buf0 [0,16K), B buf1 [16K,32K), A stage [32K,48K)
__global__ void __launch_bounds__(NTHR, 1) gemm_lse_kernel() {
    __shared__ __align__(128) char smem[49152];
    const uint32_t sb = smem_u32(smem);
    const int tid = threadIdx.x, lane = tid & 31, w = tid >> 5;
    const int wm = w >> 2, wn = w & 3;          // 4x4 warp grid, 32x32 tiles
    const int blk = blockIdx.x, rowBase = blk * BM;
    const int g = lane >> 3, r8 = lane & 7;

    // Stage A tile (swizzled) and pull fragments into registers (once).
    {
        const uint4* src = (const uint4*)(g_ah + (size_t)rowBase * DDIM);
        uint4* dstA = (uint4*)(smem + 32768);
        #pragma unroll
        for (int i = tid; i < 1024; i += NTHR) {
            int r = i >> 3, c = i & 7;
            dstA[r * 8 + (c ^ (r & 7))] = src[i];
        }
    }
    __syncthreads();

    uint32_t afr[2][4][4];                       // [mi][kstep][reg]
    #pragma unroll
    for (int mi = 0; mi < 2; mi++)
        #pragma unroll
        for (int ks = 0; ks < 4; ks++) {
            int m  = wm * 32 + mi * 16 + (g & 1) * 8 + r8;
            int kc = ks * 2 + (g >> 1);
            uint32_t addr = sb + 32768u + (uint32_t)(m * 128 + ((kc ^ (m & 7)) << 4));
            LDSM_X4(afr[mi][ks][0], afr[mi][ks][1], afr[mi][ks][2], afr[mi][ks][3], addr);
        }

    // B-fragment ldmatrix address components (per thread, fixed)
    const int kg = g & 1;
    uint32_t brow[2]; int bnlo[2];
    #pragma unroll
    for (int p = 0; p < 2; p++) {
        int n = wn * 32 + p * 16 + (g >> 1) * 8 + r8;
        brow[p] = (uint32_t)(n * 128);
        bnlo[p] = n & 7;
    }

    // Prefetch B tile 0
    {
        const uint4* src = (const uint4*)g_bh;
        #pragma unroll
        for (int i = tid; i < 1024; i += NTHR) {
            int r = i >> 3, c = i & 7;
            CP_ASYNC16(sb + (uint32_t)(r * 128 + ((c ^ (r & 7)) << 4)), src + i);
        }
        CP_COMMIT();
    }

    float s[4] = {0.f, 0.f, 0.f, 0.f};
    float pos[4] = {0.f, 0.f, 0.f, 0.f};

    #pragma unroll 1
    for (int t = 0; t < NTILES; t++) {
        const uint32_t bufb = sb + (uint32_t)((t & 1) << 14);
        if (t + 1 < NTILES) {
            const uint32_t nbuf = sb + (uint32_t)(((t + 1) & 1) << 14);
            const uint4* src = (const uint4*)(g_bh + (size_t)(t + 1) * BN * DDIM);
            #pragma unroll
            for (int i = tid; i < 1024; i += NTHR) {
                int r = i >> 3, c = i & 7;
                CP_ASYNC16(nbuf + (uint32_t)(r * 128 + ((c ^ (r & 7)) << 4)), src + i);
            }
            CP_COMMIT();
            CP_WAIT(1);                     // tile t resident, t+1 in flight
        } else {
            CP_WAIT(0);
        }
        __syncthreads();

        float c_[2][4][4];
        #pragma unroll
        for (int mi = 0; mi < 2; mi++)
            #pragma unroll
            for (int ni = 0; ni < 4; ni++)
                #pragma unroll
                for (int j = 0; j < 4; j++) c_[mi][ni][j] = 0.f;

        #pragma unroll
        for (int ks = 0; ks < 4; ks++) {
            uint32_t b[4][2];
            #pragma unroll
            for (int p = 0; p < 2; p++) {
                uint32_t addr = bufb + brow[p] +
                                (uint32_t)((((ks * 2 + kg) ^ bnlo[p])) << 4);
                LDSM_X4(b[2 * p][0], b[2 * p][1], b[2 * p + 1][0], b[2 * p + 1][1], addr);
            }
            #pragma unroll
            for (int mi = 0; mi < 2; mi++)
                #pragma unroll
                for (int ni = 0; ni < 4; ni++)
                    MMA16816(c_[mi][ni], afr[mi][ks], b[ni]);
        }

        // Diagonal (positive) capture — only the matching tile, algebraically
        // identical to the reference's [pos, masked-row] logits.
        if (t == blk && wm == wn) {
            #pragma unroll
            for (int mi = 0; mi < 2; mi++)
                #pragma unroll
                for (int ni = 0; ni < 4; ni++)
                    #pragma unroll
                    for (int j = 0; j < 4; j++) {
                        int r = wm * 32 + mi * 16 + ((j >> 1) & 1) * 8 + (lane >> 2);
                        int c = wn * 32 + ni * 8 + 2 * (lane & 3) + (j & 1);
                        if (r == c) pos[mi * 2 + (j >> 1)] = c_[mi][ni][j];
                    }
        }

        // Fused epilogue: exp2-sum (no max needed: |logit2| <= 28.9)
        #pragma unroll
        for (int mi = 0; mi < 2; mi++)
            #pragma unroll
            for (int ni = 0; ni < 4; ni++) {
                s[mi * 2 + 0] += ex2f(c_[mi][ni][0]) + ex2f(c_[mi][ni][1]);
                s[mi * 2 + 1] += ex2f(c_[mi][ni][2]) + ex2f(c_[mi][ni][3]);
            }
        __syncthreads();                    // protect buffer (t-1 parity) reuse
    }

    // ── Cross-warp reduction (overlay on dead B buffers) ──
    float* red    = (float*)smem;             // [128][16]
    float* posArr = (float*)(smem + 8192);    // [128]
    float* fin    = (float*)(smem + 10240);   // [128]
    const int q = lane >> 2, p = lane & 3;
    #pragma unroll
    for (int slot = 0; slot < 4; slot++) {
        int mi = slot >> 1, hi = slot & 1;
        int r = wm * 32 + mi * 16 + hi * 8 + q;
        red[r * 16 + wn * 4 + p] = s[slot];
        if (wm == wn && (q >> 1) == p) posArr[r] = pos[slot];
    }
    __syncthreads();
    if (tid < 128) {
        float tot = 0.f;
        #pragma unroll
        for (int i = 0; i < 16; i++) tot += red[tid * 16 + i];
        fin[tid] = (log2f(tot) - posArr[tid]) * LN2F;
    }
    __syncthreads();
    #pragma unroll
    for (int off = 64; off; off >>= 1) {
        if (tid < off) fin[tid] += fin[tid + off];
        __syncthreads();
    }
    if (tid == 0) g_partials[blk] = fin[0];
}

// ───────────────────────── Kernel 3: final reduction ────────────────────────
__global__ void finalize_kernel(float* __restrict__ out) {
    __shared__ float red[NBLOCKS];
    int tid = threadIdx.x;
    red[tid] = g_partials[tid];
    __syncthreads();
    #pragma unroll
    for (int off = 64; off; off >>= 1) {
        if (tid < off) red[tid] += red[tid + off];
        __syncthreads();
    }
    if (tid == 0) out[0] = red[0] * (1.0f / (float)NROWS);
}

// ────────────────────────────────────────────────────────────────────────────
extern "C" void kernel_launch(void* const* d_in, const int* in_sizes, int n_in,
                              void* d_out, int out_size) {
    const float* z1 = (const float*)d_in[0];
    const float* z2 = (const float*)d_in[1];
    float* out = (float*)d_out;

    normalize_kernel<<<(2 * NROWS) / 8, 256>>>(z1, z2);
    gemm_lse_kernel<<<NBLOCKS, NTHR>>>();
    finalize_kernel<<<1, NBLOCKS>>>(out);
}

// round 4
// speedup vs baseline: 7.0498x; 1.0404x over previous
#include <cuda_runtime.h>
#include <cuda_fp16.h>
#include <cstdint>
#include <math.h>

#define NROWS 16384
#define DDIM  64
#define BM    128
#define BN    128
#define NTILES   (NROWS / BN)     // 128
#define NCHUNKS  8                // 16 tiles per chunk
#define NTASKS   (NTILES * NCHUNKS)   // 1024 (rowblock x chunk)
#define GRID_P   148
#define NTHR  512
#define SCALE_A 28.853900817779268f   // log2(e)/tau
#define LN2F    0.6931471805599453f

__device__ __half g_ah[NROWS * DDIM];      // z1n * log2(e)/tau  [m][k]
__device__ __half g_bh[NROWS * DDIM];      // z2n               [n][k]
__device__ float  g_rowsum[NCHUNKS * NROWS];
__device__ float  g_pos[NROWS];
__device__ float  g_part1[64];

__device__ __forceinline__ uint32_t smem_u32(const void* p) {
    uint32_t a;
    asm("{ .reg .u64 t; cvta.to.shared.u64 t, %1; cvt.u32.u64 %0, t; }" : "=r"(a) : "l"(p));
    return a;
}
__device__ __forceinline__ float ex2f(float x) {
    float r; asm("ex2.approx.f32 %0, %1;" : "=f"(r) : "f"(x)); return r;
}
__device__ __forceinline__ float2 h2f(uint32_t u) {
    __half2 h = *reinterpret_cast<__half2*>(&u);
    return __half22float2(h);
}
#define LDSM_X4(r0, r1, r2, r3, addr) \
    asm volatile("ldmatrix.sync.aligned.m8n8.x4.shared.b16 {%0,%1,%2,%3}, [%4];" \
        : "=r"(r0), "=r"(r1), "=r"(r2), "=r"(r3) : "r"(addr))
#define MMA16816_F16(d, a, b) \
    asm volatile("mma.sync.aligned.m16n8k16.row.col.f16.f16.f16.f16 " \
        "{%0,%1}, {%2,%3,%4,%5}, {%6,%7}, {%0,%1};" \
        : "+r"((d)[0]), "+r"((d)[1]) \
        : "r"((a)[0]), "r"((a)[1]), "r"((a)[2]), "r"((a)[3]), "r"((b)[0]), "r"((b)[1]))
#define CP_ASYNC16(dst, src) \
    asm volatile("cp.async.cg.shared.global [%0], [%1], 16;" :: "r"(dst), "l"(src))
#define CP_COMMIT()  asm volatile("cp.async.commit_group;" ::: "memory")
#define CP_WAIT(n)   asm volatile("cp.async.wait_group %0;" :: "n"(n) : "memory")

// ─────────────── Kernel 1: L2-normalize + fp16 quantize + scale fold ────────
// 2 rows per warp, float4 loads.
__global__ void normalize_kernel(const float* __restrict__ z1,
                                 const float* __restrict__ z2) {
    int warp = blockIdx.x * (blockDim.x >> 5) + (threadIdx.x >> 5);
    int lane = threadIdx.x & 31;
    int row  = warp * 2 + (lane >> 4);        // global row in [0, 2*NROWS)
    int l16  = lane & 15;

    const float* src; __half* dst; float scale; int r;
    if (row < NROWS) { src = z1; dst = g_ah; r = row;          scale = SCALE_A; }
    else             { src = z2; dst = g_bh; r = row - NROWS;  scale = 1.0f;    }

    float4 v = ((const float4*)(src + (size_t)r * DDIM))[l16];
    float ss = v.x * v.x + v.y * v.y + v.z * v.z + v.w * v.w;
    #pragma unroll
    for (int off = 8; off; off >>= 1)
        ss += __shfl_xor_sync(0xffffffffu, ss, off);   // stays within 16-lane half
    float inv = scale / fmaxf(sqrtf(ss), 1e-12f);
    __half2 h0 = __floats2half2_rn(v.x * inv, v.y * inv);
    __half2 h1 = __floats2half2_rn(v.z * inv, v.w * inv);
    uint2 o = make_uint2(*(uint32_t*)&h0, *(uint32_t*)&h1);
    ((uint2*)(dst + (size_t)r * DDIM))[l16] = o;
}

// ── Kernel 2: persistent fp16-accum mma.sync GEMM + fused row exp2-sum ──────
// smem: B buf0 [0,16K), B buf1 [16K,32K), A stage [32K,48K)
__global__ void __launch_bounds__(NTHR, 1) gemm_lse_kernel() {
    __shared__ __align__(128) char smem[49152];
    const uint32_t sb = smem_u32(smem);
    const int tid = threadIdx.x, lane = tid & 31, w = tid >> 5;
    const int wm = w >> 2, wn = w & 3;          // 4x4 warp grid, 32x32 tiles
    const int g = lane >> 3, r8 = lane & 7;
    const int kg = g & 1;
    const int q = lane >> 2, p4 = lane & 3;

    // Fixed per-thread B ldmatrix address components
    uint32_t brow[2]; int bnlo[2];
    #pragma unroll
    for (int p = 0; p < 2; p++) {
        int n = wn * 32 + p * 16 + (g >> 1) * 8 + r8;
        brow[p] = (uint32_t)(n * 128);
        bnlo[p] = n & 7;
    }

    for (int task = blockIdx.x; task < NTASKS; task += GRID_P) {
        const int rb = task >> 3, ck = task & 7, t0 = ck << 4;

        // ── Stage A tile for this rowblock, re-fragment into registers ──
        {
            const uint4* asrc = (const uint4*)(g_ah + (size_t)rb * BM * DDIM);
            uint4* dstA = (uint4*)(smem + 32768);
            #pragma unroll
            for (int i = tid; i < 1024; i += NTHR) {
                int r = i >> 3, c = i & 7;
                dstA[r * 8 + (c ^ (r & 7))] = asrc[i];
            }
        }
        __syncthreads();

        uint32_t afr[2][4][4];
        #pragma unroll
        for (int mi = 0; mi < 2; mi++)
            #pragma unroll
            for (int ks = 0; ks < 4; ks++) {
                int m  = wm * 32 + mi * 16 + (g & 1) * 8 + r8;
                int kc = ks * 2 + (g >> 1);
                uint32_t addr = sb + 32768u + (uint32_t)(m * 128 + ((kc ^ (m & 7)) << 4));
                LDSM_X4(afr[mi][ks][0], afr[mi][ks][1], afr[mi][ks][2], afr[mi][ks][3], addr);
            }

        // Prefetch first B tile of this chunk -> buf0
        {
            const uint4* bs = (const uint4*)(g_bh + (size_t)t0 * BN * DDIM);
            #pragma unroll
            for (int i = tid; i < 1024; i += NTHR) {
                int r = i >> 3, c = i & 7;
                CP_ASYNC16(sb + (uint32_t)(r * 128 + ((c ^ (r & 7)) << 4)), bs + i);
            }
            CP_COMMIT();
        }

        float s[4] = {0.f, 0.f, 0.f, 0.f};

        #pragma unroll 1
        for (int it = 0; it < 16; it++) {
            const int t = t0 + it;
            const uint32_t bufb = sb + (uint32_t)((it & 1) << 14);
            if (it < 15) {
                const uint32_t nbuf = sb + (uint32_t)(((it + 1) & 1) << 14);
                const uint4* bs = (const uint4*)(g_bh + (size_t)(t + 1) * BN * DDIM);
                #pragma unroll
                for (int i = tid; i < 1024; i += NTHR) {
                    int r = i >> 3, c = i & 7;
                    CP_ASYNC16(nbuf + (uint32_t)(r * 128 + ((c ^ (r & 7)) << 4)), bs + i);
                }
                CP_COMMIT();
                CP_WAIT(1);
            } else {
                CP_WAIT(0);
            }
            __syncthreads();

            uint32_t c_[2][4][2];
            #pragma unroll
            for (int mi = 0; mi < 2; mi++)
                #pragma unroll
                for (int ni = 0; ni < 4; ni++) { c_[mi][ni][0] = 0u; c_[mi][ni][1] = 0u; }

            #pragma unroll
            for (int ks = 0; ks < 4; ks++) {
                uint32_t b[4][2];
                #pragma unroll
                for (int p = 0; p < 2; p++) {
                    uint32_t addr = bufb + brow[p] +
                                    (uint32_t)((((ks * 2 + kg) ^ bnlo[p])) << 4);
                    LDSM_X4(b[2 * p][0], b[2 * p][1], b[2 * p + 1][0], b[2 * p + 1][1], addr);
                }
                #pragma unroll
                for (int mi = 0; mi < 2; mi++)
                    #pragma unroll
                    for (int ni = 0; ni < 4; ni++)
                        MMA16816_F16(c_[mi][ni], afr[mi][ks], b[ni]);
            }

            // Diagonal (positive) capture — unique writer per row; leaving the
            // diag in the exp-sum is identical to the reference's masking.
            if (t == rb && wm == wn) {
                #pragma unroll
                for (int mi = 0; mi < 2; mi++)
                    #pragma unroll
                    for (int ni = 0; ni < 4; ni++) {
                        float2 f0 = h2f(c_[mi][ni][0]);
                        float2 f1 = h2f(c_[mi][ni][1]);
                        int r0 = wm * 32 + mi * 16 + q, r1 = r0 + 8;
                        int cb = wn * 32 + ni * 8 + 2 * p4;
                        if (r0 == cb)     g_pos[rb * BM + r0] = f0.x;
                        if (r0 == cb + 1) g_pos[rb * BM + r0] = f0.y;
                        if (r1 == cb)     g_pos[rb * BM + r1] = f1.x;
                        if (r1 == cb + 1) g_pos[rb * BM + r1] = f1.y;
                    }
            }

            // Fused epilogue: unpack + exp2-sum in fp32
            #pragma unroll
            for (int mi = 0; mi < 2; mi++)
                #pragma unroll
                for (int ni = 0; ni < 4; ni++) {
                    float2 f0 = h2f(c_[mi][ni][0]);
                    float2 f1 = h2f(c_[mi][ni][1]);
                    s[mi * 2 + 0] += ex2f(f0.x) + ex2f(f0.y);
                    s[mi * 2 + 1] += ex2f(f1.x) + ex2f(f1.y);
                }
            __syncthreads();
        }

        // ── Per-chunk row-sum reduction (scratch overlays dead buf0) ──
        float* red = (float*)smem;            // [128][16]
        #pragma unroll
        for (int slot = 0; slot < 4; slot++) {
            int mi = slot >> 1, hi = slot & 1;
            int r = wm * 32 + mi * 16 + hi * 8 + q;
            red[r * 16 + wn * 4 + p4] = s[slot];
        }
        __syncthreads();
        if (tid < BM) {
            float tot = 0.f;
            #pragma unroll
            for (int i = 0; i < 16; i++) tot += red[tid * 16 + i];
            g_rowsum[ck * NROWS + rb * BM + tid] = tot;
        }
        // Next iteration's A-stage __syncthreads fences red-reads vs buf0 reuse.
    }
}

// ───────────── Kernel 3a: per-row LSE merge + block partials ────────────────
__global__ void finalize1_kernel() {
    __shared__ float sh[256];
    int tid = threadIdx.x;
    int r = blockIdx.x * 256 + tid;
    float sum = 0.f;
    #pragma unroll
    for (int ck = 0; ck < NCHUNKS; ck++) sum += g_rowsum[ck * NROWS + r];
    float loss = (log2f(sum) - g_pos[r]) * LN2F;
    sh[tid] = loss;
    __syncthreads();
    #pragma unroll
    for (int off = 128; off; off >>= 1) {
        if (tid < off) sh[tid] += sh[tid + off];
        __syncthreads();
    }
    if (tid == 0) g_part1[blockIdx.x] = sh[0];
}

// ───────────── Kernel 3b: final scalar ──────────────────────────────────────
__global__ void finalize2_kernel(float* __restrict__ out) {
    __shared__ float sh[64];
    int tid = threadIdx.x;
    sh[tid] = g_part1[tid];
    __syncthreads();
    #pragma unroll
    for (int off = 32; off; off >>= 1) {
        if (tid < off) sh[tid] += sh[tid + off];
        __syncthreads();
    }
    if (tid == 0) out[0] = sh[0] * (1.0f / (float)NROWS);
}

// ────────────────────────────────────────────────────────────────────────────
extern "C" void kernel_launch(void* const* d_in, const int* in_sizes, int n_in,
                              void* d_out, int out_size) {
    const float* z1 = (const float*)d_in[0];
    const float* z2 = (const float*)d_in[1];
    float* out = (float*)d_out;

    normalize_kernel<<<2048, 256>>>(z1, z2);   // 2*16384 rows, 2 rows/warp
    gemm_lse_kernel<<<GRID_P, NTHR>>>();
    finalize1_kernel<<<64, 256>>>();
    finalize2_kernel<<<1, 64>>>(out);
}

// round 5
// speedup vs baseline: 7.9708x; 1.1306x over previous
#include <cuda_runtime.h>
#include <cuda_fp16.h>
#include <cstdint>
#include <math.h>

#define NROWS 16384
#define DDIM  64
#define BM    128
#define BN    128
#define NTILES   (NROWS / BN)     // 128
#define NCHUNKS  8                // 16 tiles per chunk
#define NTASKS   (NTILES * NCHUNKS)   // 1024
#define GRID_P   148
#define NTHR  512
#define SCALE_A 28.853900817779268f   // log2(e)/tau
#define LN2F    0.6931471805599453f
#define BIAS_H2 0xCA00CA00u           // packed half2(-12, -12)

__device__ __half g_ah[NROWS * DDIM];      // z1n * log2(e)/tau  [m][k]
__device__ __half g_bh[NROWS * DDIM];      // z2n               [n][k]
__device__ float  g_rowsum[NCHUNKS * NROWS];   // biased by 2^-12 (cancels)
__device__ float  g_pos[NROWS];                // biased logit (cancels)
__device__ float  g_part1[64];

__device__ __forceinline__ uint32_t smem_u32(const void* p) {
    uint32_t a;
    asm("{ .reg .u64 t; cvta.to.shared.u64 t, %1; cvt.u32.u64 %0, t; }" : "=r"(a) : "l"(p));
    return a;
}
__device__ __forceinline__ uint32_t ex2_h2(uint32_t x) {
    uint32_t r; asm("ex2.approx.f16x2 %0, %1;" : "=r"(r) : "r"(x)); return r;
}
__device__ __forceinline__ uint32_t hadd2u(uint32_t a, uint32_t b) {
    uint32_t r; asm("add.rn.f16x2 %0, %1, %2;" : "=r"(r) : "r"(a), "r"(b)); return r;
}
__device__ __forceinline__ float2 h2f(uint32_t u) {
    __half2 h = *reinterpret_cast<__half2*>(&u);
    return __half22float2(h);
}
#define LDSM_X4(r0, r1, r2, r3, addr) \
    asm volatile("ldmatrix.sync.aligned.m8n8.x4.shared.b16 {%0,%1,%2,%3}, [%4];" \
        : "=r"(r0), "=r"(r1), "=r"(r2), "=r"(r3) : "r"(addr))
#define MMA16816_F16(d, a, b) \
    asm volatile("mma.sync.aligned.m16n8k16.row.col.f16.f16.f16.f16 " \
        "{%0,%1}, {%2,%3,%4,%5}, {%6,%7}, {%0,%1};" \
        : "+r"((d)[0]), "+r"((d)[1]) \
        : "r"((a)[0]), "r"((a)[1]), "r"((a)[2]), "r"((a)[3]), "r"((b)[0]), "r"((b)[1]))
#define CP_ASYNC16(dst, src) \
    asm volatile("cp.async.cg.shared.global [%0], [%1], 16;" :: "r"(dst), "l"(src))
#define CP_COMMIT()  asm volatile("cp.async.commit_group;" ::: "memory")
#define CP_WAIT(n)   asm volatile("cp.async.wait_group %0;" :: "n"(n) : "memory")

// ─────────────── Kernel 1: L2-normalize + fp16 quantize + scale fold ────────
__global__ void normalize_kernel(const float* __restrict__ z1,
                                 const float* __restrict__ z2) {
    int warp = blockIdx.x * (blockDim.x >> 5) + (threadIdx.x >> 5);
    int lane = threadIdx.x & 31;
    int row  = warp * 2 + (lane >> 4);
    int l16  = lane & 15;

    const float* src; __half* dst; float scale; int r;
    if (row < NROWS) { src = z1; dst = g_ah; r = row;          scale = SCALE_A; }
    else             { src = z2; dst = g_bh; r = row - NROWS;  scale = 1.0f;    }

    float4 v = ((const float4*)(src + (size_t)r * DDIM))[l16];
    float ss = v.x * v.x + v.y * v.y + v.z * v.z + v.w * v.w;
    #pragma unroll
    for (int off = 8; off; off >>= 1)
        ss += __shfl_xor_sync(0xffffffffu, ss, off);
    float inv = scale / fmaxf(sqrtf(ss), 1e-12f);
    __half2 h0 = __floats2half2_rn(v.x * inv, v.y * inv);
    __half2 h1 = __floats2half2_rn(v.z * inv, v.w * inv);
    uint2 o = make_uint2(*(uint32_t*)&h0, *(uint32_t*)&h1);
    ((uint2*)(dst + (size_t)r * DDIM))[l16] = o;
}

// ── Kernel 2: persistent fp16 mma.sync GEMM + all-fp16 exp2 epilogue ────────
// smem: B buf0 [0,16K), B buf1 [16K,32K), A stage [32K,48K)
__global__ void __launch_bounds__(NTHR, 1) gemm_lse_kernel() {
    __shared__ __align__(128) char smem[49152];
    const uint32_t sb = smem_u32(smem);
    const int tid = threadIdx.x, lane = tid & 31, w = tid >> 5;
    const int wm = w >> 2, wn = w & 3;
    const int g = lane >> 3, r8 = lane & 7;
    const int kg = g & 1;
    const int q = lane >> 2, p4 = lane & 3;

    uint32_t brow[2]; int bnlo[2];
    #pragma unroll
    for (int p = 0; p < 2; p++) {
        int n = wn * 32 + p * 16 + (g >> 1) * 8 + r8;
        brow[p] = (uint32_t)(n * 128);
        bnlo[p] = n & 7;
    }

    for (int task = blockIdx.x; task < NTASKS; task += GRID_P) {
        const int rb = task >> 3, ck = task & 7, t0 = ck << 4;

        {   // Stage A tile (swizzled)
            const uint4* asrc = (const uint4*)(g_ah + (size_t)rb * BM * DDIM);
            uint4* dstA = (uint4*)(smem + 32768);
            #pragma unroll
            for (int i = tid; i < 1024; i += NTHR) {
                int r = i >> 3, c = i & 7;
                dstA[r * 8 + (c ^ (r & 7))] = asrc[i];
            }
        }
        __syncthreads();

        uint32_t afr[2][4][4];
        #pragma unroll
        for (int mi = 0; mi < 2; mi++)
            #pragma unroll
            for (int ks = 0; ks < 4; ks++) {
                int m  = wm * 32 + mi * 16 + (g & 1) * 8 + r8;
                int kc = ks * 2 + (g >> 1);
                uint32_t addr = sb + 32768u + (uint32_t)(m * 128 + ((kc ^ (m & 7)) << 4));
                LDSM_X4(afr[mi][ks][0], afr[mi][ks][1], afr[mi][ks][2], afr[mi][ks][3], addr);
            }

        {   // Prefetch first B tile -> buf0
            const uint4* bs = (const uint4*)(g_bh + (size_t)t0 * BN * DDIM);
            #pragma unroll
            for (int i = tid; i < 1024; i += NTHR) {
                int r = i >> 3, c = i & 7;
                CP_ASYNC16(sb + (uint32_t)(r * 128 + ((c ^ (r & 7)) << 4)), bs + i);
            }
            CP_COMMIT();
        }

        float s[4] = {0.f, 0.f, 0.f, 0.f};
        uint32_t hacc[4] = {0u, 0u, 0u, 0u};     // f16x2 partial exp-sums

        #pragma unroll 1
        for (int it = 0; it < 16; it++) {
            const int t = t0 + it;
            const uint32_t bufb = sb + (uint32_t)((it & 1) << 14);
            if (it < 15) {
                const uint32_t nbuf = sb + (uint32_t)(((it + 1) & 1) << 14);
                const uint4* bs = (const uint4*)(g_bh + (size_t)(t + 1) * BN * DDIM);
                #pragma unroll
                for (int i = tid; i < 1024; i += NTHR) {
                    int r = i >> 3, c = i & 7;
                    CP_ASYNC16(nbuf + (uint32_t)(r * 128 + ((c ^ (r & 7)) << 4)), bs + i);
                }
                CP_COMMIT();
                CP_WAIT(1);
            } else {
                CP_WAIT(0);
            }
            __syncthreads();

            // Accumulators pre-biased to -12: MMA yields logit-12 directly.
            uint32_t c_[2][4][2];
            #pragma unroll
            for (int mi = 0; mi < 2; mi++)
                #pragma unroll
                for (int ni = 0; ni < 4; ni++) {
                    c_[mi][ni][0] = BIAS_H2; c_[mi][ni][1] = BIAS_H2;
                }

            #pragma unroll
            for (int ks = 0; ks < 4; ks++) {
                uint32_t b[4][2];
                #pragma unroll
                for (int p = 0; p < 2; p++) {
                    uint32_t addr = bufb + brow[p] +
                                    (uint32_t)((((ks * 2 + kg) ^ bnlo[p])) << 4);
                    LDSM_X4(b[2 * p][0], b[2 * p][1], b[2 * p + 1][0], b[2 * p + 1][1], addr);
                }
                #pragma unroll
                for (int mi = 0; mi < 2; mi++)
                    #pragma unroll
                    for (int ni = 0; ni < 4; ni++)
                        MMA16816_F16(c_[mi][ni], afr[mi][ks], b[ni]);
            }

            // Diagonal capture: store the BIASED logit (bias cancels in lse-pos)
            if (t == rb && wm == wn) {
                #pragma unroll
                for (int mi = 0; mi < 2; mi++)
                    #pragma unroll
                    for (int ni = 0; ni < 4; ni++) {
                        float2 f0 = h2f(c_[mi][ni][0]);
                        float2 f1 = h2f(c_[mi][ni][1]);
                        int r0 = wm * 32 + mi * 16 + q, r1 = r0 + 8;
                        int cb = wn * 32 + ni * 8 + 2 * p4;
                        if (r0 == cb)     g_pos[rb * BM + r0] = f0.x;
                        if (r0 == cb + 1) g_pos[rb * BM + r0] = f0.y;
                        if (r1 == cb)     g_pos[rb * BM + r1] = f1.x;
                        if (r1 == cb + 1) g_pos[rb * BM + r1] = f1.y;
                    }
            }

            // All-fp16 epilogue: ex2.f16x2 on raw MMA regs, HADD2 trees
            #pragma unroll
            for (int mi = 0; mi < 2; mi++)
                #pragma unroll
                for (int j = 0; j < 2; j++) {
                    uint32_t e0 = ex2_h2(c_[mi][0][j]);
                    uint32_t e1 = ex2_h2(c_[mi][1][j]);
                    uint32_t e2 = ex2_h2(c_[mi][2][j]);
                    uint32_t e3 = ex2_h2(c_[mi][3][j]);
                    uint32_t tsum = hadd2u(hadd2u(e0, e1), hadd2u(e2, e3));
                    hacc[mi * 2 + j] = hadd2u(hacc[mi * 2 + j], tsum);
                }
            if (it & 1) {                    // drain fp16 partials every 2 tiles
                #pragma unroll
                for (int slot = 0; slot < 4; slot++) {
                    float2 f = h2f(hacc[slot]);
                    s[slot] += f.x + f.y;
                    hacc[slot] = 0u;
                }
            }
            __syncthreads();
        }

        // Per-chunk row-sum reduction (overlay on dead buf0)
        float* red = (float*)smem;
        #pragma unroll
        for (int slot = 0; slot < 4; slot++) {
            int mi = slot >> 1, hi = slot & 1;
            int r = wm * 32 + mi * 16 + hi * 8 + q;
            red[r * 16 + wn * 4 + p4] = s[slot];
        }
        __syncthreads();
        if (tid < BM) {
            float tot = 0.f;
            #pragma unroll
            for (int i = 0; i < 16; i++) tot += red[tid * 16 + i];
            g_rowsum[ck * NROWS + rb * BM + tid] = tot;
        }
    }
}

// ───────────── Kernel 3a: per-row LSE merge + block partials ────────────────
__global__ void finalize1_kernel() {
    __shared__ float sh[256];
    int tid = threadIdx.x;
    int r = blockIdx.x * 256 + tid;
    float sum = 0.f;
    #pragma unroll
    for (int ck = 0; ck < NCHUNKS; ck++) sum += g_rowsum[ck * NROWS + r];
    // both sum and pos carry the 2^-12 / -12 bias -> cancels exactly
    sh[tid] = (log2f(sum) - g_pos[r]) * LN2F;
    __syncthreads();
    #pragma unroll
    for (int off = 128; off; off >>= 1) {
        if (tid < off) sh[tid] += sh[tid + off];
        __syncthreads();
    }
    if (tid == 0) g_part1[blockIdx.x] = sh[0];
}

// ───────────── Kernel 3b: final scalar ──────────────────────────────────────
__global__ void finalize2_kernel(float* __restrict__ out) {
    __shared__ float sh[64];
    int tid = threadIdx.x;
    sh[tid] = g_part1[tid];
    __syncthreads();
    #pragma unroll
    for (int off = 32; off; off >>= 1) {
        if (tid < off) sh[tid] += sh[tid + off];
        __syncthreads();
    }
    if (tid == 0) out[0] = sh[0] * (1.0f / (float)NROWS);
}

// ────────────────────────────────────────────────────────────────────────────
extern "C" void kernel_launch(void* const* d_in, const int* in_sizes, int n_in,
                              void* d_out, int out_size) {
    const float* z1 = (const float*)d_in[0];
    const float* z2 = (const float*)d_in[1];
    float* out = (float*)d_out;

    normalize_kernel<<<2048, 256>>>(z1, z2);
    gemm_lse_kernel<<<GRID_P, NTHR>>>();
    finalize1_kernel<<<64, 256>>>();
    finalize2_kernel<<<1, 64>>>(out);
}